// round 8
// baseline (speedup 1.0000x reference)
#include <cuda_runtime.h>
#include <cstdint>

#define K_DIM   784
#define H_DIM   1024
#define O_DIM   10
#define B_SIZE  128
#define T_STEPS 200
#define M_TOTAL (B_SIZE * T_STEPS)   // 25600
#define BETA    0.95f

#define BMg 128
#define BNg 128
#define BKg 16
#define KTILES (K_DIM / BKg)         // 49, exact

typedef unsigned long long ull;

__device__ float    g_cur1[(size_t)M_TOTAL * H_DIM];
__device__ unsigned g_spk[(size_t)M_TOTAL * (H_DIM / 32)];
__device__ float    g_cur2T[(size_t)O_DIM * M_TOTAL];    // transposed [o][m]

// ---------------- packed fp32x2 helpers (sm_103a FFMA2) ----------------
__device__ __forceinline__ ull ffma2(ull a, ull b, ull c) {
    ull d;
    asm("fma.rn.f32x2 %0, %1, %2, %3;" : "=l"(d) : "l"(a), "l"(b), "l"(c));
    return d;
}
__device__ __forceinline__ void unpack2(ull v, float& x, float& y) {
    asm("mov.b64 {%0, %1}, %2;" : "=f"(x), "=f"(y) : "l"(v));
}

// ---------------------------------------------------------------------------
// GEMM1: cur1[M,H] = x[M,K] @ w1[H,K]^T + b1. Bitwise fp32: every accumulator
// lane is a strict k=0..783 sequential FMA chain (== reference SGEMM order).
// Diagonal FFMA2 pairing: acc[mp][j] = (c[2mp][j], c[2mp+1][(j+1)&7]), so the
// a-pair (A[2mp],A[2mp+1]) and b-pair (b_j,b_{j+1&7}) are both aligned 64-bit
// smem loads — zero packing MOVs. Odd-j b-pairs come from a skewed copy Bk.
// ---------------------------------------------------------------------------
__global__ __launch_bounds__(256, 2) void gemm1_ffma2(
    const float* __restrict__ x, const float* __restrict__ w1,
    const float* __restrict__ bias)
{
    __shared__ float As[BKg][BMg];    // [k][m]
    __shared__ float Bs[BKg][BNg];    // [k][n]
    __shared__ float Bk[BKg][BNg];    // skewed: Bk[k][g*8+p] = Bs[k][g*8+((p+1)&7)]

    const int tid = threadIdx.x;
    const int tr  = tid & 15;         // m-block: rows tr*8 .. tr*8+7
    const int tc  = tid >> 4;         // n-block: cols tc*8 .. tc*8+7
    const int bm  = blockIdx.y * BMg;
    const int bn  = blockIdx.x * BNg;
    const int lr  = tid >> 1;         // load row 0..127
    const int lk  = (tid & 1) * 8;    // load k offset 0 or 8
    // b value at column lr lands in Bk at column:
    const int skc = (lr & ~7) | ((lr + 7) & 7);

    const float* ag = x  + (size_t)(bm + lr) * K_DIM + lk;
    const float* bg = w1 + (size_t)(bn + lr) * K_DIM + lk;

    // prologue: stage tile 0 in registers
    float4 a0 = *(const float4*)(ag);
    float4 a1 = *(const float4*)(ag + 4);
    float4 b0 = *(const float4*)(bg);
    float4 b1 = *(const float4*)(bg + 4);

    ull acc[4][8];
    #pragma unroll
    for (int i = 0; i < 4; i++)
        #pragma unroll
        for (int j = 0; j < 8; j++) acc[i][j] = 0ULL;

    for (int t = 0; t < KTILES; t++) {
        // store staged tile to smem (transposed to [k][row])
        As[lk + 0][lr] = a0.x; As[lk + 1][lr] = a0.y;
        As[lk + 2][lr] = a0.z; As[lk + 3][lr] = a0.w;
        As[lk + 4][lr] = a1.x; As[lk + 5][lr] = a1.y;
        As[lk + 6][lr] = a1.z; As[lk + 7][lr] = a1.w;
        Bs[lk + 0][lr] = b0.x; Bs[lk + 1][lr] = b0.y;
        Bs[lk + 2][lr] = b0.z; Bs[lk + 3][lr] = b0.w;
        Bs[lk + 4][lr] = b1.x; Bs[lk + 5][lr] = b1.y;
        Bs[lk + 6][lr] = b1.z; Bs[lk + 7][lr] = b1.w;
        Bk[lk + 0][skc] = b0.x; Bk[lk + 1][skc] = b0.y;
        Bk[lk + 2][skc] = b0.z; Bk[lk + 3][skc] = b0.w;
        Bk[lk + 4][skc] = b1.x; Bk[lk + 5][skc] = b1.y;
        Bk[lk + 6][skc] = b1.z; Bk[lk + 7][skc] = b1.w;
        __syncthreads();

        // stage next tile (latency hidden under the 16 k-steps)
        if (t + 1 < KTILES) {
            const float* an  = ag + (size_t)(t + 1) * BKg;
            const float* bn_ = bg + (size_t)(t + 1) * BKg;
            a0 = *(const float4*)(an);
            a1 = *(const float4*)(an + 4);
            b0 = *(const float4*)(bn_);
            b1 = *(const float4*)(bn_ + 4);
        }

        #pragma unroll
        for (int k = 0; k < BKg; k++) {
            // a-pairs: (m0,m1),(m2,m3),(m4,m5),(m6,m7) — direct 64-bit loads
            const ulonglong2 apA = *(const ulonglong2*)&As[k][tr * 8];
            const ulonglong2 apB = *(const ulonglong2*)&As[k][tr * 8 + 4];
            // b-pairs even j: (b0,b1),(b2,b3),(b4,b5),(b6,b7)
            const ulonglong2 beA = *(const ulonglong2*)&Bs[k][tc * 8];
            const ulonglong2 beB = *(const ulonglong2*)&Bs[k][tc * 8 + 4];
            // b-pairs odd j: (b1,b2),(b3,b4),(b5,b6),(b7,b0)
            const ulonglong2 boA = *(const ulonglong2*)&Bk[k][tc * 8];
            const ulonglong2 boB = *(const ulonglong2*)&Bk[k][tc * 8 + 4];

            const ull ap[4] = {apA.x, apA.y, apB.x, apB.y};
            const ull bp[8] = {beA.x, boA.x, beA.y, boA.y,
                               beB.x, boB.x, beB.y, boB.y};
            #pragma unroll
            for (int mp = 0; mp < 4; mp++)
                #pragma unroll
                for (int j = 0; j < 8; j++)
                    acc[mp][j] = ffma2(ap[mp], bp[j], acc[mp][j]);
        }
        __syncthreads();
    }

    // Epilogue: undo diagonal pairing, add bias, store.
    // acc[mp][j].lo = c[2mp][j]; acc[mp][j].hi = c[2mp+1][(j+1)&7]
    const int colb = bn + tc * 8;
    float bv[8];
    #pragma unroll
    for (int j = 0; j < 8; j++) bv[j] = bias[colb + j];

    #pragma unroll
    for (int mp = 0; mp < 4; mp++) {
        float r0[8], r1[8];
        #pragma unroll
        for (int j = 0; j < 8; j++) {
            float lo, hi;
            unpack2(acc[mp][j], lo, hi);
            r0[j]            = lo + bv[j];
            r1[(j + 1) & 7]  = hi;            // bias added after reorder
        }
        #pragma unroll
        for (int j = 0; j < 8; j++) r1[j] += bv[j];

        const int row = bm + tr * 8 + mp * 2;
        float* d0 = g_cur1 + (size_t)row * H_DIM + colb;
        float* d1 = d0 + H_DIM;
        *(float4*)(d0)     = make_float4(r0[0], r0[1], r0[2], r0[3]);
        *(float4*)(d0 + 4) = make_float4(r0[4], r0[5], r0[6], r0[7]);
        *(float4*)(d1)     = make_float4(r1[0], r1[1], r1[2], r1[3]);
        *(float4*)(d1 + 4) = make_float4(r1[4], r1[5], r1[6], r1[7]);
    }
}

// ---------------------------------------------------------------------------
// Phase A: mem1 scan, one thread per (b,h); bitwise fma chain; ballot bitmask.
// ---------------------------------------------------------------------------
__global__ __launch_bounds__(256) void phaseA_kernel() {
    const int gid = blockIdx.x * 256 + threadIdx.x;
    const int b = gid >> 10;
    const int h = gid & 1023;
    const int lane = threadIdx.x & 31;

    const float* cp = g_cur1 + (size_t)b * T_STEPS * H_DIM + h;
    unsigned* sp = g_spk + (size_t)b * T_STEPS * 32 + (h >> 5);

    float mem = 0.f, spk = 0.f;
    float c = cp[0];
    for (int t = 0; t < T_STEPS; t++) {
        float cn = (t + 1 < T_STEPS) ? cp[(size_t)(t + 1) * H_DIM] : 0.f;
        mem = fmaf(BETA, mem, c) - spk;
        spk = (mem > 1.0f) ? 1.0f : 0.0f;
        unsigned bal = __ballot_sync(0xffffffffu, mem > 1.0f);
        if (lane == 0) sp[(size_t)t * 32] = bal;
        c = cn;
    }
}

// ---------------------------------------------------------------------------
// Phase B: cur2T[o][m] = sum_h spk[m][h]*w2[o][h], h strictly sequential.
// ---------------------------------------------------------------------------
__global__ __launch_bounds__(256) void phaseB_kernel(const float* __restrict__ w2) {
    __shared__ float w2s[H_DIM * O_DIM];
    for (int i = threadIdx.x; i < H_DIM * O_DIM; i += 256) {
        const int o = i / H_DIM, h = i % H_DIM;
        w2s[h * O_DIM + o] = w2[i];
    }
    __syncthreads();

    const int warp = blockIdx.x * 8 + (threadIdx.x >> 5);
    const int row  = warp * 32 + (threadIdx.x & 31);

    float acc[O_DIM];
    #pragma unroll
    for (int o = 0; o < O_DIM; o++) acc[o] = 0.f;

    const unsigned* sw = g_spk + (size_t)row * 32;
    for (int wb = 0; wb < 32; wb++) {
        const unsigned bits = sw[wb];
        #pragma unroll 8
        for (int j = 0; j < 32; j++) {
            const float f = ((bits >> j) & 1u) ? 1.0f : 0.0f;
            const float* wp = &w2s[(wb * 32 + j) * O_DIM];
            #pragma unroll
            for (int o = 0; o < O_DIM; o++)
                acc[o] = fmaf(f, wp[o], acc[o]);
        }
    }
    #pragma unroll
    for (int o = 0; o < O_DIM; o++)
        g_cur2T[(size_t)o * M_TOTAL + row] = acc[o];
}

// ---------------------------------------------------------------------------
// Phase C: mem2 scan per (b,o); cur2 transposed so t-reads are contiguous.
// ---------------------------------------------------------------------------
__global__ void phaseC_kernel(const float* __restrict__ b2,
                              float* __restrict__ out_spk,
                              float* __restrict__ out_mem) {
    const int id = blockIdx.x * 128 + threadIdx.x;
    if (id >= B_SIZE * O_DIM) return;
    const int b = id / O_DIM;
    const int o = id % O_DIM;

    const float bias = b2[o];
    const float* cp = g_cur2T + (size_t)o * M_TOTAL + (size_t)b * T_STEPS;
    float* os = out_spk + (size_t)b * T_STEPS * O_DIM + o;
    float* om = out_mem + (size_t)b * T_STEPS * O_DIM + o;

    float mem = 0.f, spk = 0.f;
    for (int t0 = 0; t0 < T_STEPS; t0 += 8) {
        const float4 v0 = *(const float4*)(cp + t0);
        const float4 v1 = *(const float4*)(cp + t0 + 4);
        const float c[8] = {v0.x, v0.y, v0.z, v0.w, v1.x, v1.y, v1.z, v1.w};
        #pragma unroll
        for (int i = 0; i < 8; i++) {
            mem = fmaf(BETA, mem, c[i] + bias) - spk;
            spk = (mem > 1.0f) ? 1.0f : 0.0f;
            os[(size_t)(t0 + i) * O_DIM] = spk;
            om[(size_t)(t0 + i) * O_DIM] = mem;
        }
    }
}

// ---------------------------------------------------------------------------
extern "C" void kernel_launch(void* const* d_in, const int* in_sizes, int n_in,
                              void* d_out, int out_size)
{
    const float* x  = (const float*)d_in[0];
    const float* w1 = (const float*)d_in[1];
    const float* b1 = (const float*)d_in[2];
    const float* w2 = (const float*)d_in[3];
    const float* b2 = (const float*)d_in[4];
    float* out = (float*)d_out;

    dim3 gg(H_DIM / BNg, M_TOTAL / BMg);        // (8, 200)
    gemm1_ffma2<<<gg, 256>>>(x, w1, b1);

    phaseA_kernel<<<(B_SIZE * H_DIM) / 256, 256>>>();
    phaseB_kernel<<<M_TOTAL / 256, 256>>>(w2);
    phaseC_kernel<<<(B_SIZE * O_DIM + 127) / 128, 128>>>(
        b2, out, out + (size_t)B_SIZE * T_STEPS * O_DIM);
}

// round 9
// speedup vs baseline: 1.2580x; 1.2580x over previous
#include <cuda_runtime.h>
#include <cstdint>

#define K_DIM   784
#define H_DIM   1024
#define O_DIM   10
#define B_SIZE  128
#define T_STEPS 200
#define M_TOTAL (B_SIZE * T_STEPS)   // 25600
#define BETA    0.95f

#define BMg 128
#define BNg 128
#define BKg 16
#define KTILES (K_DIM / BKg)         // 49, exact

typedef unsigned long long ull;

__device__ float    g_cur1[(size_t)M_TOTAL * H_DIM];
__device__ unsigned g_spk[(size_t)M_TOTAL * (H_DIM / 32)];
__device__ float    g_cur2T[(size_t)O_DIM * M_TOTAL];

// ---------------- packed fp32x2 (sm_103a FFMA2) ----------------
__device__ __forceinline__ ull ffma2(ull a, ull b, ull c) {
    ull d;
    asm("fma.rn.f32x2 %0, %1, %2, %3;" : "=l"(d) : "l"(a), "l"(b), "l"(c));
    return d;
}
__device__ __forceinline__ void unpack2(ull v, float& x, float& y) {
    asm("mov.b64 {%0, %1}, %2;" : "=f"(x), "=f"(y) : "l"(v));
}
// 16B-chunk swizzle for As: conflict-free both for STS (by m) and LDS (by tr)
#define SWZA(ch) ((ch) ^ ((ch) >> 3))

// ---------------------------------------------------------------------------
// GEMM1: cur1[M,H] = x[M,K] @ w1[H,K]^T + b1. Bitwise fp32 (strict k-seq FMA
// chain per output, bias at end). FFMA2 with zero packing MOVs:
//   a-operand: natural adjacent-m pair from swizzled As  (LDS.128 -> 2 pairs)
//   b-operand: duplicated pair (b,b) from Bd             (LDS.128 -> 2 pairs)
// acc[mp][j] = (c[2mp][j], c[2mp+1][j]).
// ---------------------------------------------------------------------------
__global__ __launch_bounds__(256, 2) void gemm1_ffma2(
    const float* __restrict__ x, const float* __restrict__ w1,
    const float* __restrict__ bias)
{
    __shared__ float As[BKg * BMg];       // swizzled [k][m], 8KB
    __shared__ float Bd[BKg * BNg * 2];   // duplicated [k][2n], 16KB

    const int tid = threadIdx.x;
    const int tr  = tid & 15;          // m-block: rows tr*8..tr*8+7
    const int tc  = tid >> 4;          // n-block: cols tc*8..tc*8+7
    const int bm  = blockIdx.y * BMg;
    const int bn  = blockIdx.x * BNg;
    const int lr  = tid >> 1;          // load row 0..127
    const int lk  = (tid & 1) * 8;     // load k offset 0 or 8
    const int par = tid & 1;           // store-order parity (Bd conflicts)
    const int axor = (lk >> 3) * 16;   // k-bank rotation for As stores

    // per-thread compile-time-ish constants
    const int a_st_base = SWZA(lr >> 2) * 4 + (lr & 3);   // word within k-row
    const int a_ld_c0   = SWZA(tr * 2) * 4;               // read chunk bases
    const int a_ld_c1   = SWZA(tr * 2 + 1) * 4;

    const float* ag = x  + (size_t)(bm + lr) * K_DIM + lk;
    const float* bg = w1 + (size_t)(bn + lr) * K_DIM + lk;

    float4 a0 = *(const float4*)(ag);
    float4 a1 = *(const float4*)(ag + 4);
    float4 b0 = *(const float4*)(bg);
    float4 b1 = *(const float4*)(bg + 4);

    ull acc[4][8];
    #pragma unroll
    for (int i = 0; i < 4; i++)
        #pragma unroll
        for (int j = 0; j < 8; j++) acc[i][j] = 0ULL;

    for (int t = 0; t < KTILES; t++) {
        // ---- As store: word = k*128 + (a_st_base ^ axor); conflict-free ----
        {
            const float av[8] = {a0.x, a0.y, a0.z, a0.w, a1.x, a1.y, a1.z, a1.w};
            #pragma unroll
            for (int i = 0; i < 8; i++)
                As[(lk + i) * BMg + (a_st_base ^ axor)] = av[i];
        }
        // ---- Bd store: value at words 2n+par then 2n+(1-par); conflict-free ----
        {
            const float bvv[8] = {b0.x, b0.y, b0.z, b0.w, b1.x, b1.y, b1.z, b1.w};
            #pragma unroll
            for (int i = 0; i < 8; i++) {
                float* p = &Bd[(lk + i) * (BNg * 2) + 2 * lr];
                p[par]     = bvv[i];
                p[1 - par] = bvv[i];
            }
        }
        __syncthreads();

        if (t + 1 < KTILES) {
            const float* an  = ag + (size_t)(t + 1) * BKg;
            const float* bn_ = bg + (size_t)(t + 1) * BKg;
            a0 = *(const float4*)(an);
            a1 = *(const float4*)(an + 4);
            b0 = *(const float4*)(bn_);
            b1 = *(const float4*)(bn_ + 4);
        }

        #pragma unroll
        for (int k = 0; k < BKg; k++) {
            const int kxor = (k >> 3) * 16;
            // A: two LDS.128 -> 4 natural m-pairs (m0,m1),(m2,m3),(m4,m5),(m6,m7)
            const ulonglong2 apA = *(const ulonglong2*)&As[k * BMg + (a_ld_c0 ^ kxor)];
            const ulonglong2 apB = *(const ulonglong2*)&As[k * BMg + (a_ld_c1 ^ kxor)];
            // B: four LDS.128 (broadcast) -> 8 duplicated pairs (b_j,b_j)
            const float* bk = &Bd[k * (BNg * 2) + tc * 16];
            const ulonglong2 bq0 = *(const ulonglong2*)(bk);
            const ulonglong2 bq1 = *(const ulonglong2*)(bk + 4);
            const ulonglong2 bq2 = *(const ulonglong2*)(bk + 8);
            const ulonglong2 bq3 = *(const ulonglong2*)(bk + 12);

            const ull ap[4] = {apA.x, apA.y, apB.x, apB.y};
            const ull bp[8] = {bq0.x, bq0.y, bq1.x, bq1.y,
                               bq2.x, bq2.y, bq3.x, bq3.y};
            #pragma unroll
            for (int mp = 0; mp < 4; mp++)
                #pragma unroll
                for (int j = 0; j < 8; j++)
                    acc[mp][j] = ffma2(ap[mp], bp[j], acc[mp][j]);
        }
        __syncthreads();
    }

    // Epilogue: acc[mp][j] = (c[tr*8+2mp][j], c[tr*8+2mp+1][j]); add bias, store.
    const int colb = bn + tc * 8;
    float bv[8];
    #pragma unroll
    for (int j = 0; j < 8; j++) bv[j] = bias[colb + j];

    #pragma unroll
    for (int mp = 0; mp < 4; mp++) {
        float r0[8], r1[8];
        #pragma unroll
        for (int j = 0; j < 8; j++) {
            float lo, hi;
            unpack2(acc[mp][j], lo, hi);
            r0[j] = lo + bv[j];
            r1[j] = hi + bv[j];
        }
        const int row = bm + tr * 8 + mp * 2;
        float* d0 = g_cur1 + (size_t)row * H_DIM + colb;
        float* d1 = d0 + H_DIM;
        *(float4*)(d0)     = make_float4(r0[0], r0[1], r0[2], r0[3]);
        *(float4*)(d0 + 4) = make_float4(r0[4], r0[5], r0[6], r0[7]);
        *(float4*)(d1)     = make_float4(r1[0], r1[1], r1[2], r1[3]);
        *(float4*)(d1 + 4) = make_float4(r1[4], r1[5], r1[6], r1[7]);
    }
}

// ---------------------------------------------------------------------------
// Phase A: mem1 scan, one thread per (b,h); ballot bitmask.
// ---------------------------------------------------------------------------
__global__ __launch_bounds__(256) void phaseA_kernel() {
    const int gid = blockIdx.x * 256 + threadIdx.x;
    const int b = gid >> 10;
    const int h = gid & 1023;
    const int lane = threadIdx.x & 31;

    const float* cp = g_cur1 + (size_t)b * T_STEPS * H_DIM + h;
    unsigned* sp = g_spk + (size_t)b * T_STEPS * 32 + (h >> 5);

    float mem = 0.f, spk = 0.f;
    float c = cp[0];
    for (int t = 0; t < T_STEPS; t++) {
        float cn = (t + 1 < T_STEPS) ? cp[(size_t)(t + 1) * H_DIM] : 0.f;
        mem = fmaf(BETA, mem, c) - spk;
        spk = (mem > 1.0f) ? 1.0f : 0.0f;
        unsigned bal = __ballot_sync(0xffffffffu, mem > 1.0f);
        if (lane == 0) sp[(size_t)t * 32] = bal;
        c = cn;
    }
}

// ---------------------------------------------------------------------------
// Phase B: cur2T[o][m] = sum_h spk[m][h]*w2[o][h], h strictly sequential.
// ---------------------------------------------------------------------------
__global__ __launch_bounds__(256) void phaseB_kernel(const float* __restrict__ w2) {
    __shared__ float w2s[H_DIM * O_DIM];
    for (int i = threadIdx.x; i < H_DIM * O_DIM; i += 256) {
        const int o = i / H_DIM, h = i % H_DIM;
        w2s[h * O_DIM + o] = w2[i];
    }
    __syncthreads();

    const int warp = blockIdx.x * 8 + (threadIdx.x >> 5);
    const int row  = warp * 32 + (threadIdx.x & 31);

    float acc[O_DIM];
    #pragma unroll
    for (int o = 0; o < O_DIM; o++) acc[o] = 0.f;

    const unsigned* sw = g_spk + (size_t)row * 32;
    for (int wb = 0; wb < 32; wb++) {
        const unsigned bits = sw[wb];
        #pragma unroll 8
        for (int j = 0; j < 32; j++) {
            const float f = ((bits >> j) & 1u) ? 1.0f : 0.0f;
            const float* wp = &w2s[(wb * 32 + j) * O_DIM];
            #pragma unroll
            for (int o = 0; o < O_DIM; o++)
                acc[o] = fmaf(f, wp[o], acc[o]);
        }
    }
    #pragma unroll
    for (int o = 0; o < O_DIM; o++)
        g_cur2T[(size_t)o * M_TOTAL + row] = acc[o];
}

// ---------------------------------------------------------------------------
// Phase C: mem2 scan per (b,o); contiguous t-reads from cur2T.
// ---------------------------------------------------------------------------
__global__ void phaseC_kernel(const float* __restrict__ b2,
                              float* __restrict__ out_spk,
                              float* __restrict__ out_mem) {
    const int id = blockIdx.x * 32 + threadIdx.x;
    if (id >= B_SIZE * O_DIM) return;
    const int b = id / O_DIM;
    const int o = id % O_DIM;

    const float bias = b2[o];
    const float* cp = g_cur2T + (size_t)o * M_TOTAL + (size_t)b * T_STEPS;
    float* os = out_spk + (size_t)b * T_STEPS * O_DIM + o;
    float* om = out_mem + (size_t)b * T_STEPS * O_DIM + o;

    float mem = 0.f, spk = 0.f;
    for (int t0 = 0; t0 < T_STEPS; t0 += 8) {
        const float4 v0 = *(const float4*)(cp + t0);
        const float4 v1 = *(const float4*)(cp + t0 + 4);
        const float c[8] = {v0.x, v0.y, v0.z, v0.w, v1.x, v1.y, v1.z, v1.w};
        #pragma unroll
        for (int i = 0; i < 8; i++) {
            mem = fmaf(BETA, mem, c[i] + bias) - spk;
            spk = (mem > 1.0f) ? 1.0f : 0.0f;
            os[(size_t)(t0 + i) * O_DIM] = spk;
            om[(size_t)(t0 + i) * O_DIM] = mem;
        }
    }
}

// ---------------------------------------------------------------------------
extern "C" void kernel_launch(void* const* d_in, const int* in_sizes, int n_in,
                              void* d_out, int out_size)
{
    const float* x  = (const float*)d_in[0];
    const float* w1 = (const float*)d_in[1];
    const float* b1 = (const float*)d_in[2];
    const float* w2 = (const float*)d_in[3];
    const float* b2 = (const float*)d_in[4];
    float* out = (float*)d_out;

    dim3 gg(H_DIM / BNg, M_TOTAL / BMg);        // (8, 200)
    gemm1_ffma2<<<gg, 256>>>(x, w1, b1);

    phaseA_kernel<<<(B_SIZE * H_DIM) / 256, 256>>>();
    phaseB_kernel<<<M_TOTAL / 256, 256>>>(w2);
    phaseC_kernel<<<(B_SIZE * O_DIM + 31) / 32, 32>>>(
        b2, out, out + (size_t)B_SIZE * T_STEPS * O_DIM);
}